// round 11
// baseline (speedup 1.0000x reference)
#include <cuda_runtime.h>
#include <stdint.h>

// Algebraic feature expansion:
//   out[:, 0:16]    = x
//   out[:, 16:136]  = pair products  x[a]*x[b]   (lex order)
//   out[:, 136:696] = triple products x[a]*x[b]*x[c] (lex order)
// B=262144 rows, 696 out cols. HBM-store + L1tex co-bound.
//
// v11: v10 (one tile per block, grid=ntiles=16384, constant tables — the
// oversubscription win) + R8's pair factoring, whose per-tile costs are now
// one sync per BLOCK instead of per tile: all 120 pair products per row are
// staged in smem, then every output is a product of TWO smem operands
// (triple (a,b,c) = pair(a,b) * x[c], same association as jnp.prod).
// Per chunk: 8 LDS + 4 FMUL (was 12 LDS + 8 FMUL); 8 operand pointers.

#define NC    16
#define NPAIR 120
#define OUTC  696
#define Q4    174          // OUTC / 4
#define RTILE 16           // rows per tile (262144/16 = 16384 blocks)
#define EXT   140          // ext row: x[0..15], 1.0 @16, pad, pairs @20..139
#define POFF  20
#define BLK   192          // 6 warps; threads [0,174) compute, [0,64) load

// ---- Compile-time tables ----
struct Tab  { unsigned v[OUTC]; };    // off1 | off2<<16 into ext row
struct PTab { unsigned v[NPAIR]; };   // a | b<<8

static constexpr int pair_idx(int a, int b) {
    // lexicographic index of pair (a,b), a<b, over NC columns
    return a * (2 * NC - a - 1) / 2 + (b - a - 1);
}

static constexpr Tab make_tab() {
    Tab t{};
    int col = 0;
    for (int a = 0; a < NC; a++)
        t.v[col++] = (unsigned)a | (16u << 16);                       // x[a]*1.0
    for (int a = 0; a < NC; a++)
        for (int b = a + 1; b < NC; b++)
            t.v[col++] = (unsigned)a | ((unsigned)b << 16);           // x[a]*x[b]
    for (int a = 0; a < NC; a++)
        for (int b = a + 1; b < NC; b++)
            for (int c = b + 1; c < NC; c++)
                t.v[col++] = (unsigned)(POFF + pair_idx(a, b))
                           | ((unsigned)c << 16);                     // pair*x[c]
    return t;
}

static constexpr PTab make_ptab() {
    PTab t{};
    int p = 0;
    for (int a = 0; a < NC; a++)
        for (int b = a + 1; b < NC; b++)
            t.v[p++] = (unsigned)a | ((unsigned)b << 8);
    return t;
}

__constant__ Tab  ctab  = make_tab();
__constant__ PTab cptab = make_ptab();

__global__ __launch_bounds__(BLK) void algebraic_expand_kernel(
    const float* __restrict__ x,
    float4* __restrict__ out4,
    int nrows)
{
    __shared__ __align__(16) float xs[RTILE][EXT];

    const int t    = threadIdx.x;
    const int row0 = blockIdx.x * RTILE;

    // ---- Kick off the tile load first (LDG in flight during decode) ----
    float4 ld;
    const bool loader = (t < RTILE * NC / 4);     // 64 loader threads
    const int lr = t >> 2;
    const int lc = (t & 3) << 2;
    const bool do_ld = loader && (row0 + lr < nrows);
    if (do_ld)
        ld = reinterpret_cast<const float4*>(x + (size_t)row0 * NC)[t];

    // ---- Decode this thread's fixed chunk from __constant__ (overlaps LDG) ----
    const bool active = (t < Q4);
    const float* base = &xs[0][0];
    const float *q0 = base, *q1 = base, *q2 = base, *q3 = base,
                *q4 = base, *q5 = base, *q6 = base, *q7 = base;
    if (active) {
        const uint4 pk = reinterpret_cast<const uint4*>(ctab.v)[t];
        q0 = base + (pk.x & 0xffffu);  q1 = base + (pk.x >> 16);
        q2 = base + (pk.y & 0xffffu);  q3 = base + (pk.y >> 16);
        q4 = base + (pk.z & 0xffffu);  q5 = base + (pk.z >> 16);
        q6 = base + (pk.w & 0xffffu);  q7 = base + (pk.w >> 16);
    }

    // ---- Stage the raw tile ----
    if (do_ld)
        *reinterpret_cast<float4*>(&xs[lr][lc]) = ld;
    if (t < RTILE) xs[t][16] = 1.0f;   // dummy operand
    __syncthreads();

    // ---- Stage all pair products: 120 pairs x 16 rows = 1920 items ----
    #pragma unroll
    for (int s = t; s < NPAIR * RTILE; s += BLK) {   // exactly 10 per thread
        const int p = s >> 4;
        const int r = s & 15;
        const unsigned ab = cptab.v[p];
        xs[r][POFF + p] = xs[r][ab & 255u] * xs[r][ab >> 8];
    }
    __syncthreads();

    if (!active) return;

    float4* ob = out4 + (size_t)row0 * Q4 + t;

    if (row0 + RTILE <= nrows) {
        // fast path: full tile, all offsets compile-time immediates
        #pragma unroll
        for (int r = 0; r < RTILE; r++) {
            const int o = r * EXT;
            float4 v;
            v.x = q0[o] * q1[o];
            v.y = q2[o] * q3[o];
            v.z = q4[o] * q5[o];
            v.w = q6[o] * q7[o];
            __stcs(&ob[(size_t)r * Q4], v);
        }
    } else {
        const int rem = nrows - row0;
        for (int r = 0; r < rem; r++) {
            const int o = r * EXT;
            float4 v;
            v.x = q0[o] * q1[o];
            v.y = q2[o] * q3[o];
            v.z = q4[o] * q5[o];
            v.w = q6[o] * q7[o];
            __stcs(&ob[(size_t)r * Q4], v);
        }
    }
}

extern "C" void kernel_launch(void* const* d_in, const int* in_sizes, int n_in,
                              void* d_out, int out_size)
{
    const float* x = (const float*)d_in[0];
    const int nrows = in_sizes[0] / NC;

    const int ntiles = (nrows + RTILE - 1) / RTILE;   // 16384 for B=262144
    algebraic_expand_kernel<<<ntiles, BLK>>>(x, (float4*)d_out, nrows);
}